// round 1
// baseline (speedup 1.0000x reference)
#include <cuda_runtime.h>
#include <math.h>
#include <stdint.h>

// Problem constants
#define BB   2
#define SS   2048
#define EE   2048
#define HH   16
#define DD   128
#define MTOT (BB*SS)      // 4096
#define NQKV (3*EE)       // 6144
#define KDIM EE           // 2048

// ---------------------------------------------------------------------------
// Scratch (device globals; no allocation allowed)
// ---------------------------------------------------------------------------
__device__ float g_q[(size_t)BB*HH*SS*DD];     // [B,H,S,D]
__device__ float g_k[(size_t)BB*HH*SS*DD];
__device__ float g_v[(size_t)BB*HH*SS*DD];
__device__ float g_ctx[(size_t)MTOT*EE];       // [B*S, E]
__device__ float g_cos[SS*64];
__device__ float g_sin[SS*64];

// ---------------------------------------------------------------------------
// RoPE cos/sin table. Matches the JAX reference: phase = fp32(s) * fp32(inv_freq)
// (fp32 multiply), then accurate cos/sin of that fp32 value (double trig).
// ---------------------------------------------------------------------------
__global__ void rope_table_kernel()
{
    int idx = blockIdx.x * blockDim.x + threadIdx.x;
    if (idx >= SS * 64) return;
    int j = idx & 63;
    int s = idx >> 6;
    double denom = pow(10000.0, ((double)(2 * j)) / 128.0);
    float invf = (float)(1.0 / denom);
    float ph = (float)s * invf;          // fp32 product like the reference
    double p = (double)ph;
    g_cos[idx] = (float)cos(p);
    g_sin[idx] = (float)sin(p);
}

// ---------------------------------------------------------------------------
// Apply ESM-style RoPE in place to q and k ([B,H,S,D], half-split rotate).
// One thread per (tensor, b, h, s, pair j).
// ---------------------------------------------------------------------------
__global__ void rope_apply_kernel()
{
    int idx = blockIdx.x * blockDim.x + threadIdx.x;   // < 2*BB*HH*SS*64 = 8388608
    int j      = idx & 63;
    int r      = idx >> 6;                // 0..131071
    int bhs    = r & (BB*HH*SS - 1);      // BB*HH*SS = 65536 (pow2)
    int tensor = r >> 16;
    int s      = bhs & (SS - 1);

    float* p = tensor ? g_k : g_q;
    size_t base = (size_t)bhs * DD;
    float c  = g_cos[(s << 6) + j];
    float sn = g_sin[(s << 6) + j];
    float x1 = p[base + j];
    float x2 = p[base + j + 64];
    p[base + j]      = x1 * c - x2 * sn;
    p[base + j + 64] = x2 * c + x1 * sn;
}

// ---------------------------------------------------------------------------
// 128x128x16 fp32 SGEMM:  C[m,n] = dot(A[m,:], W[n,:]) + bias[n]
// A: [M,K] row-major, W: [N,K] row-major (both K-contiguous -> coalesced).
// MODE 0: scatter epilogue into g_q/g_k/g_v ([B,H,S,D]).
// MODE 1: plain row-major C [M,N].
// ---------------------------------------------------------------------------
template<int MODE>
__global__ __launch_bounds__(256) void gemm128(
    const float* __restrict__ A, const float* __restrict__ W,
    const float* __restrict__ bias, float* __restrict__ C,
    int M, int N, int K)
{
    __shared__ float As[16][132];   // [k][m], padded row
    __shared__ float Bs[16][132];   // [k][n]

    const int tid = threadIdx.x;
    const int ty = tid >> 4;        // 0..15 (m group)
    const int tx = tid & 15;        // 0..15 (n group)
    const int m0 = blockIdx.y << 7;
    const int n0 = blockIdx.x << 7;

    float acc[8][8];
#pragma unroll
    for (int i = 0; i < 8; i++)
#pragma unroll
        for (int j = 0; j < 8; j++) acc[i][j] = 0.f;

    for (int kt = 0; kt < K; kt += 16) {
#pragma unroll
        for (int i = 0; i < 2; i++) {
            int idx = tid + (i << 8);         // 0..511
            int row = idx >> 2;               // 0..127
            int c4  = (idx & 3) << 2;         // 0,4,8,12
            float4 va = *(const float4*)&A[(size_t)(m0 + row) * K + kt + c4];
            As[c4 + 0][row] = va.x; As[c4 + 1][row] = va.y;
            As[c4 + 2][row] = va.z; As[c4 + 3][row] = va.w;
            float4 vb = *(const float4*)&W[(size_t)(n0 + row) * K + kt + c4];
            Bs[c4 + 0][row] = vb.x; Bs[c4 + 1][row] = vb.y;
            Bs[c4 + 2][row] = vb.z; Bs[c4 + 3][row] = vb.w;
        }
        __syncthreads();

#pragma unroll
        for (int k = 0; k < 16; k++) {
            float a[8], b[8];
            *(float4*)&a[0] = *(const float4*)&As[k][ty * 8];
            *(float4*)&a[4] = *(const float4*)&As[k][ty * 8 + 4];
            *(float4*)&b[0] = *(const float4*)&Bs[k][tx * 8];
            *(float4*)&b[4] = *(const float4*)&Bs[k][tx * 8 + 4];
#pragma unroll
            for (int i = 0; i < 8; i++)
#pragma unroll
                for (int j = 0; j < 8; j++)
                    acc[i][j] += a[i] * b[j];
        }
        __syncthreads();
    }

#pragma unroll
    for (int i = 0; i < 8; i++) {
        int m = m0 + ty * 8 + i;
#pragma unroll
        for (int jb = 0; jb < 8; jb += 4) {
            int n = n0 + tx * 8 + jb;
            float4 bv = *(const float4*)&bias[n];
            float4 rr;
            rr.x = acc[i][jb + 0] + bv.x;
            rr.y = acc[i][jb + 1] + bv.y;
            rr.z = acc[i][jb + 2] + bv.z;
            rr.w = acc[i][jb + 3] + bv.w;
            if (MODE == 0) {
                int which = n >> 11;          // 0:q 1:k 2:v
                int h = (n >> 7) & (HH - 1);
                int d = n & (DD - 1);
                int b = m >> 11;
                int s = m & (SS - 1);
                float* dst = (which == 0) ? g_q : (which == 1) ? g_k : g_v;
                *(float4*)&dst[(((size_t)b * HH + h) * SS + s) * DD + d] = rr;
            } else {
                *(float4*)&C[(size_t)m * N + n] = rr;
            }
        }
    }
}

// ---------------------------------------------------------------------------
// Flash attention, fp32 FFMA. CTA = (b, h, 128-row q tile). 256 threads.
// smem: Qs [128d][136] (d-major, transposed), Ks [128d][136] (aliased by
// Ps [128k][136] after scores), Vs [128k][128d]. Online softmax in registers.
// ---------------------------------------------------------------------------
#define ATT_SMEM_FLOATS (128*136*2 + 128*128)   // 51200 floats = 204800 B

__global__ __launch_bounds__(256, 1) void attn_kernel()
{
    extern __shared__ float sm[];
    float* Qs = sm;                 // [d][q], stride 136
    float* Ks = sm + 128 * 136;     // [d][k], stride 136; later Ps [k][q]
    float* Vs = sm + 2 * 128 * 136; // [k][d], stride 128

    const int tid = threadIdx.x;
    const int gy = tid >> 4;   // 0..15 : q-row group (8 rows each)
    const int gx = tid & 15;   // 0..15 : k-col / d-col group (8 each)
    const int q0 = blockIdx.x << 7;
    const int h  = blockIdx.y;
    const int b  = blockIdx.z;

    const size_t head_off = ((size_t)b * HH + h) * SS * DD;
    const float* Qg = g_q + head_off + (size_t)q0 * DD;
    const float* Kg = g_k + head_off;
    const float* Vg = g_v + head_off;

    // Load Q tile transposed: Qs[d][q]
#pragma unroll
    for (int it = 0; it < 16; it++) {
        int idx = tid + (it << 8);       // 0..4095
        int row = idx >> 5;              // q row 0..127
        int c4  = (idx & 31) << 2;       // d 0..124
        float4 v = *(const float4*)&Qg[(size_t)row * DD + c4];
        Qs[(c4 + 0) * 136 + row] = v.x;
        Qs[(c4 + 1) * 136 + row] = v.y;
        Qs[(c4 + 2) * 136 + row] = v.z;
        Qs[(c4 + 3) * 136 + row] = v.w;
    }

    float m_i[8], l_i[8], O[8][8];
#pragma unroll
    for (int i = 0; i < 8; i++) {
        m_i[i] = -1e30f; l_i[i] = 0.f;
#pragma unroll
        for (int j = 0; j < 8; j++) O[i][j] = 0.f;
    }

    const float scale = 0.088388347648318447f;   // 1/sqrt(128)

    for (int kt = 0; kt < SS; kt += 128) {
        __syncthreads();   // prev PV done (Ps/Vs free); Q tile visible

        // Load K tile transposed, V tile natural
#pragma unroll
        for (int it = 0; it < 16; it++) {
            int idx = tid + (it << 8);
            int row = idx >> 5;
            int c4  = (idx & 31) << 2;
            float4 kv = *(const float4*)&Kg[(size_t)(kt + row) * DD + c4];
            Ks[(c4 + 0) * 136 + row] = kv.x;
            Ks[(c4 + 1) * 136 + row] = kv.y;
            Ks[(c4 + 2) * 136 + row] = kv.z;
            Ks[(c4 + 3) * 136 + row] = kv.w;
            float4 vv = *(const float4*)&Vg[(size_t)(kt + row) * DD + c4];
            *(float4*)&Vs[row * DD + c4] = vv;
        }
        __syncthreads();

        // Scores: c[8q][8k] = Q @ K^T
        float c[8][8];
#pragma unroll
        for (int i = 0; i < 8; i++)
#pragma unroll
            for (int j = 0; j < 8; j++) c[i][j] = 0.f;

#pragma unroll 2
        for (int d = 0; d < DD; d++) {
            float a[8], bb[8];
            *(float4*)&a[0]  = *(const float4*)&Qs[d * 136 + gy * 8];
            *(float4*)&a[4]  = *(const float4*)&Qs[d * 136 + gy * 8 + 4];
            *(float4*)&bb[0] = *(const float4*)&Ks[d * 136 + gx * 8];
            *(float4*)&bb[4] = *(const float4*)&Ks[d * 136 + gx * 8 + 4];
#pragma unroll
            for (int i = 0; i < 8; i++)
#pragma unroll
                for (int j = 0; j < 8; j++)
                    c[i][j] += a[i] * bb[j];
        }

        // Online softmax (rows owned by the 16 lanes sharing gy)
#pragma unroll
        for (int i = 0; i < 8; i++) {
#pragma unroll
            for (int j = 0; j < 8; j++) c[i][j] *= scale;
            float mx = c[i][0];
#pragma unroll
            for (int j = 1; j < 8; j++) mx = fmaxf(mx, c[i][j]);
#pragma unroll
            for (int o = 1; o < 16; o <<= 1)
                mx = fmaxf(mx, __shfl_xor_sync(0xffffffffu, mx, o));
            float mn  = fmaxf(m_i[i], mx);
            float fac = __expf(m_i[i] - mn);
            float rs  = 0.f;
#pragma unroll
            for (int j = 0; j < 8; j++) {
                c[i][j] = __expf(c[i][j] - mn);
                rs += c[i][j];
            }
#pragma unroll
            for (int o = 1; o < 16; o <<= 1)
                rs += __shfl_xor_sync(0xffffffffu, rs, o);
            l_i[i] = l_i[i] * fac + rs;
            m_i[i] = mn;
#pragma unroll
            for (int j = 0; j < 8; j++) O[i][j] *= fac;
        }

        __syncthreads();   // everyone done reading Ks before P overwrites it

        // Stage P into smem (Ps aliases Ks): Ps[k][q]
#pragma unroll
        for (int i = 0; i < 8; i++)
#pragma unroll
            for (int j = 0; j < 8; j++)
                Ks[(gx * 8 + j) * 136 + gy * 8 + i] = c[i][j];
        __syncthreads();

        // O += P @ V
#pragma unroll 2
        for (int kk = 0; kk < 128; kk++) {
            float pp[8], vv[8];
            *(float4*)&pp[0] = *(const float4*)&Ks[kk * 136 + gy * 8];
            *(float4*)&pp[4] = *(const float4*)&Ks[kk * 136 + gy * 8 + 4];
            *(float4*)&vv[0] = *(const float4*)&Vs[kk * DD + gx * 8];
            *(float4*)&vv[4] = *(const float4*)&Vs[kk * DD + gx * 8 + 4];
#pragma unroll
            for (int i = 0; i < 8; i++)
#pragma unroll
                for (int j = 0; j < 8; j++)
                    O[i][j] += pp[i] * vv[j];
        }
    }

    // Normalize and write ctx [B*S, E] (E-col = h*128 + d)
#pragma unroll
    for (int i = 0; i < 8; i++) {
        float inv = 1.f / l_i[i];
        int s = q0 + gy * 8 + i;
        size_t rowoff = ((size_t)(b * SS + s)) * EE + h * DD + gx * 8;
        float4 r0, r1;
        r0.x = O[i][0] * inv; r0.y = O[i][1] * inv;
        r0.z = O[i][2] * inv; r0.w = O[i][3] * inv;
        r1.x = O[i][4] * inv; r1.y = O[i][5] * inv;
        r1.z = O[i][6] * inv; r1.w = O[i][7] * inv;
        *(float4*)&g_ctx[rowoff]     = r0;
        *(float4*)&g_ctx[rowoff + 4] = r1;
    }
}

// ---------------------------------------------------------------------------
// Launch
// ---------------------------------------------------------------------------
extern "C" void kernel_launch(void* const* d_in, const int* in_sizes, int n_in,
                              void* d_out, int out_size)
{
    (void)in_sizes; (void)n_in; (void)out_size;
    const float* x      = (const float*)d_in[0];
    const float* Wqkv_w = (const float*)d_in[1];
    const float* Wqkv_b = (const float*)d_in[2];
    const float* out_w  = (const float*)d_in[3];
    const float* out_b  = (const float*)d_in[4];
    float* out = (float*)d_out;

    float* ctx_ptr = nullptr;
    cudaGetSymbolAddress((void**)&ctx_ptr, g_ctx);

    cudaFuncSetAttribute(attn_kernel, cudaFuncAttributeMaxDynamicSharedMemorySize,
                         ATT_SMEM_FLOATS * (int)sizeof(float));

    rope_table_kernel<<<(SS * 64 + 255) / 256, 256>>>();

    gemm128<0><<<dim3(NQKV / 128, MTOT / 128), 256>>>(
        x, Wqkv_w, Wqkv_b, nullptr, MTOT, NQKV, KDIM);

    rope_apply_kernel<<<(2 * BB * HH * SS * 64) / 256, 256>>>();

    attn_kernel<<<dim3(SS / 128, HH, BB), 256, ATT_SMEM_FLOATS * sizeof(float)>>>();

    gemm128<1><<<dim3(EE / 128, MTOT / 128), 256>>>(
        ctx_ptr, out_w, out_b, out, MTOT, EE, KDIM);
}

// round 3
// speedup vs baseline: 1.3818x; 1.3818x over previous
#include <cuda_runtime.h>
#include <cuda_bf16.h>
#include <math.h>
#include <stdint.h>

// Problem constants
#define BB   2
#define SS   2048
#define EE   2048
#define HH   16
#define DD   128
#define MTOT (BB*SS)      // 4096
#define NQKV (3*EE)       // 6144
#define KDIM EE           // 2048

// ---------------------------------------------------------------------------
// Scratch (device globals; no allocation allowed)
// ---------------------------------------------------------------------------
__device__ float g_q[(size_t)BB*HH*SS*DD];     // [B,H,S,D] fp32
__device__ float g_k[(size_t)BB*HH*SS*DD];
__device__ float g_v[(size_t)BB*HH*SS*DD];
__device__ float g_cos[SS*64];
__device__ float g_sin[SS*64];

__device__ __nv_bfloat16 g_xh[(size_t)MTOT*KDIM];
__device__ __nv_bfloat16 g_xl[(size_t)MTOT*KDIM];
__device__ __nv_bfloat16 g_wqh[(size_t)NQKV*KDIM];
__device__ __nv_bfloat16 g_wql[(size_t)NQKV*KDIM];
__device__ __nv_bfloat16 g_owh[(size_t)EE*KDIM];
__device__ __nv_bfloat16 g_owl[(size_t)EE*KDIM];
__device__ __nv_bfloat16 g_ch[(size_t)MTOT*EE];   // ctx hi
__device__ __nv_bfloat16 g_cl[(size_t)MTOT*EE];   // ctx lo

// ---------------------------------------------------------------------------
// Baseline-PTX helpers (sm_80+: mma.sync, ldmatrix, cp.async)
// ---------------------------------------------------------------------------
__device__ __forceinline__ uint32_t smem_u32(const void* p) {
    uint32_t a;
    asm("{ .reg .u64 t; cvta.to.shared.u64 t, %1; cvt.u32.u64 %0, t; }"
        : "=r"(a) : "l"(p));
    return a;
}

#define CP_ASYNC16(dst, src) \
    asm volatile("cp.async.cg.shared.global [%0], [%1], 16;" \
                 :: "r"(dst), "l"(src) : "memory")
#define CP_COMMIT() asm volatile("cp.async.commit_group;" ::: "memory")

__device__ __forceinline__ void ldmatrix_x4(uint32_t* r, uint32_t addr) {
    asm volatile("ldmatrix.sync.aligned.m8n8.x4.shared.b16 {%0,%1,%2,%3}, [%4];"
                 : "=r"(r[0]), "=r"(r[1]), "=r"(r[2]), "=r"(r[3]) : "r"(addr));
}

__device__ __forceinline__ void mma16816(float* c,
    uint32_t a0, uint32_t a1, uint32_t a2, uint32_t a3, uint32_t b0, uint32_t b1)
{
    asm volatile(
        "mma.sync.aligned.m16n8k16.row.col.f32.bf16.bf16.f32 "
        "{%0,%1,%2,%3}, {%4,%5,%6,%7}, {%8,%9}, {%0,%1,%2,%3};"
        : "+f"(c[0]), "+f"(c[1]), "+f"(c[2]), "+f"(c[3])
        : "r"(a0), "r"(a1), "r"(a2), "r"(a3), "r"(b0), "r"(b1));
}

// ---------------------------------------------------------------------------
// fp32 -> (hi, lo) bf16 split
// ---------------------------------------------------------------------------
__global__ void split_kernel(const float* __restrict__ src,
                             __nv_bfloat16* __restrict__ hi,
                             __nv_bfloat16* __restrict__ lo, int n)
{
    int i4 = (blockIdx.x * blockDim.x + threadIdx.x) << 2;
    if (i4 >= n) return;
    float4 v = *(const float4*)(src + i4);
    float xs[4] = {v.x, v.y, v.z, v.w};
    __nv_bfloat16 h[4], l[4];
#pragma unroll
    for (int q = 0; q < 4; q++) {
        h[q] = __float2bfloat16_rn(xs[q]);
        l[q] = __float2bfloat16_rn(xs[q] - __bfloat162float(h[q]));
    }
    *(uint2*)(hi + i4) = *(uint2*)h;
    *(uint2*)(lo + i4) = *(uint2*)l;
}

// ---------------------------------------------------------------------------
// RoPE table + apply (unchanged)
// ---------------------------------------------------------------------------
__global__ void rope_table_kernel()
{
    int idx = blockIdx.x * blockDim.x + threadIdx.x;
    if (idx >= SS * 64) return;
    int j = idx & 63;
    int s = idx >> 6;
    double denom = pow(10000.0, ((double)(2 * j)) / 128.0);
    float invf = (float)(1.0 / denom);
    float ph = (float)s * invf;
    double p = (double)ph;
    g_cos[idx] = (float)cos(p);
    g_sin[idx] = (float)sin(p);
}

__global__ void rope_apply_kernel()
{
    int idx = blockIdx.x * blockDim.x + threadIdx.x;
    int j      = idx & 63;
    int r      = idx >> 6;
    int bhs    = r & (BB*HH*SS - 1);
    int tensor = r >> 16;
    int s      = bhs & (SS - 1);

    float* p = tensor ? g_k : g_q;
    size_t base = (size_t)bhs * DD;
    float c  = g_cos[(s << 6) + j];
    float sn = g_sin[(s << 6) + j];
    float x1 = p[base + j];
    float x2 = p[base + j + 64];
    p[base + j]      = x1 * c - x2 * sn;
    p[base + j + 64] = x2 * c + x1 * sn;
}

// ---------------------------------------------------------------------------
// mma.sync bf16x3 GEMM: C[m,n] = dot(A[m,:], W[n,:]) + bias[n]
//   A,W given as pre-split hi/lo bf16, [rows][K] row-major.
//   C = Ah*Bh + Al*Bh + Ah*Bl   (fp32 accumulators)
// Tile: CTA 128x128, warp 64x32, K-chunk 32, 3-stage cp.async pipeline.
// MODE 0: scatter into g_q/g_k/g_v.  MODE 1: row-major C fp32.
// ---------------------------------------------------------------------------
#define GK_CHUNK   32
#define TILE_BYTES 10240            // 128 rows * 80B (32 bf16 + 8 pad)
#define STAGE_BYTES (4*TILE_BYTES)  // Ah, Al, Bh, Bl
#define GSTAGES    3
#define GEMM_SMEM  (GSTAGES*STAGE_BYTES)   // 122880 B

__device__ __forceinline__ void gemm_load_stage(
    uint32_t stg, const __nv_bfloat16* const* tp, int K, int kt, int tid)
{
#pragma unroll
    for (int t = 0; t < 4; t++) {
        const __nv_bfloat16* p = tp[t];
#pragma unroll
        for (int i = 0; i < 2; i++) {
            int slot = tid + (i << 8);      // 0..511
            int row  = slot >> 2;           // 0..127
            int c    = slot & 3;            // 16B chunk
            uint32_t dst = stg + t * TILE_BYTES + row * 80 + c * 16;
            const void* src = p + (size_t)row * K + kt + c * 8;
            CP_ASYNC16(dst, src);
        }
    }
    CP_COMMIT();
}

template<int MODE>
__global__ __launch_bounds__(256) void gemm_mma(
    const __nv_bfloat16* __restrict__ Ah, const __nv_bfloat16* __restrict__ Al,
    const __nv_bfloat16* __restrict__ Bh, const __nv_bfloat16* __restrict__ Bl,
    const float* __restrict__ bias, float* __restrict__ C,
    int M, int N, int K)
{
    extern __shared__ char smch[];
    const uint32_t sbase = smem_u32(smch);
    const int tid  = threadIdx.x;
    const int wid  = tid >> 5;
    const int lane = tid & 31;
    const int wm   = wid & 1;        // 2 M-groups of 64
    const int wn   = wid >> 1;       // 4 N-groups of 32
    const int m0   = blockIdx.y << 7;
    const int n0   = blockIdx.x << 7;

    const __nv_bfloat16* tp[4] = {
        Ah + (size_t)m0 * K, Al + (size_t)m0 * K,
        Bh + (size_t)n0 * K, Bl + (size_t)n0 * K };

    float c[4][4][4];
#pragma unroll
    for (int i = 0; i < 4; i++)
#pragma unroll
        for (int j = 0; j < 4; j++)
#pragma unroll
            for (int q = 0; q < 4; q++) c[i][j][q] = 0.f;

    const int T = K / GK_CHUNK;      // 64

    // prologue: stages 0..2
    gemm_load_stage(sbase + 0 * STAGE_BYTES, tp, K, 0 * GK_CHUNK, tid);
    gemm_load_stage(sbase + 1 * STAGE_BYTES, tp, K, 1 * GK_CHUNK, tid);
    gemm_load_stage(sbase + 2 * STAGE_BYTES, tp, K, 2 * GK_CHUNK, tid);

    const int rsel = lane & 15;
    const int csel = (lane >> 4) << 3;

#pragma unroll 1
    for (int t = 0; t < T; t++) {
        int rem = (T - 1) - t;
        if (rem >= 2)      asm volatile("cp.async.wait_group 2;" ::: "memory");
        else if (rem == 1) asm volatile("cp.async.wait_group 1;" ::: "memory");
        else               asm volatile("cp.async.wait_group 0;" ::: "memory");
        __syncthreads();

        const uint32_t stg = sbase + (t % GSTAGES) * STAGE_BYTES;
        const uint32_t aA[3] = { stg, stg + TILE_BYTES, stg };
        const uint32_t aB[3] = { stg + 2*TILE_BYTES, stg + 2*TILE_BYTES,
                                 stg + 3*TILE_BYTES };

#pragma unroll
        for (int p = 0; p < 3; p++) {
#pragma unroll
            for (int k16 = 0; k16 < 2; k16++) {
                uint32_t a[4][4], b[2][4];
#pragma unroll
                for (int i = 0; i < 4; i++)
                    ldmatrix_x4(a[i], aA[p] + (wm*64 + i*16 + rsel)*80
                                       + (csel + k16*16)*2);
#pragma unroll
                for (int j16 = 0; j16 < 2; j16++)
                    ldmatrix_x4(b[j16], aB[p] + (wn*32 + j16*16 + rsel)*80
                                         + (csel + k16*16)*2);
#pragma unroll
                for (int i = 0; i < 4; i++)
#pragma unroll
                    for (int j16 = 0; j16 < 2; j16++) {
                        mma16816(c[i][j16*2+0], a[i][0], a[i][1], a[i][2], a[i][3],
                                 b[j16][0], b[j16][2]);
                        mma16816(c[i][j16*2+1], a[i][0], a[i][1], a[i][2], a[i][3],
                                 b[j16][1], b[j16][3]);
                    }
            }
        }
        __syncthreads();
        if (t + 3 < T)
            gemm_load_stage(sbase + ((t+3) % GSTAGES) * STAGE_BYTES,
                            tp, K, (t+3) * GK_CHUNK, tid);
    }

    // ---- epilogue ----
#pragma unroll
    for (int i = 0; i < 4; i++) {
        int rowA = m0 + wm*64 + i*16 + (lane >> 2);
#pragma unroll
        for (int j = 0; j < 4; j++) {
            int col = n0 + wn*32 + j*8 + (lane & 3)*2;
            float b0 = bias[col], b1 = bias[col+1];
            float2 lo2 = make_float2(c[i][j][0] + b0, c[i][j][1] + b1);
            float2 hi2 = make_float2(c[i][j][2] + b0, c[i][j][3] + b1);
#pragma unroll
            for (int half = 0; half < 2; half++) {
                int row = rowA + half*8;
                float2 v = half ? hi2 : lo2;
                if (MODE == 0) {
                    int which = col >> 11;
                    int h = (col >> 7) & (HH - 1);
                    int d = col & (DD - 1);
                    int bb = row >> 11;
                    int s = row & (SS - 1);
                    float* dst = (which == 0) ? g_q : (which == 1) ? g_k : g_v;
                    *(float2*)&dst[(((size_t)bb * HH + h) * SS + s) * DD + d] = v;
                } else {
                    *(float2*)&C[(size_t)row * N + col] = v;
                }
            }
        }
    }
}

// ---------------------------------------------------------------------------
// Flash attention, fp32 FFMA (epilogue now writes ctx as hi/lo bf16)
// ---------------------------------------------------------------------------
#define ATT_SMEM_FLOATS (128*136*2 + 128*128)   // 204800 B

__global__ __launch_bounds__(256, 1) void attn_kernel()
{
    extern __shared__ float smf[];
    float* Qs = smf;
    float* Ks = smf + 128 * 136;
    float* Vs = smf + 2 * 128 * 136;

    const int tid = threadIdx.x;
    const int gy = tid >> 4;
    const int gx = tid & 15;
    const int q0 = blockIdx.x << 7;
    const int h  = blockIdx.y;
    const int b  = blockIdx.z;

    const size_t head_off = ((size_t)b * HH + h) * SS * DD;
    const float* Qg = g_q + head_off + (size_t)q0 * DD;
    const float* Kg = g_k + head_off;
    const float* Vg = g_v + head_off;

#pragma unroll
    for (int it = 0; it < 16; it++) {
        int idx = tid + (it << 8);
        int row = idx >> 5;
        int c4  = (idx & 31) << 2;
        float4 v = *(const float4*)&Qg[(size_t)row * DD + c4];
        Qs[(c4 + 0) * 136 + row] = v.x;
        Qs[(c4 + 1) * 136 + row] = v.y;
        Qs[(c4 + 2) * 136 + row] = v.z;
        Qs[(c4 + 3) * 136 + row] = v.w;
    }

    float m_i[8], l_i[8], O[8][8];
#pragma unroll
    for (int i = 0; i < 8; i++) {
        m_i[i] = -1e30f; l_i[i] = 0.f;
#pragma unroll
        for (int j = 0; j < 8; j++) O[i][j] = 0.f;
    }

    const float scale = 0.088388347648318447f;

    for (int kt = 0; kt < SS; kt += 128) {
        __syncthreads();
#pragma unroll
        for (int it = 0; it < 16; it++) {
            int idx = tid + (it << 8);
            int row = idx >> 5;
            int c4  = (idx & 31) << 2;
            float4 kv = *(const float4*)&Kg[(size_t)(kt + row) * DD + c4];
            Ks[(c4 + 0) * 136 + row] = kv.x;
            Ks[(c4 + 1) * 136 + row] = kv.y;
            Ks[(c4 + 2) * 136 + row] = kv.z;
            Ks[(c4 + 3) * 136 + row] = kv.w;
            float4 vv = *(const float4*)&Vg[(size_t)(kt + row) * DD + c4];
            *(float4*)&Vs[row * DD + c4] = vv;
        }
        __syncthreads();

        float c[8][8];
#pragma unroll
        for (int i = 0; i < 8; i++)
#pragma unroll
            for (int j = 0; j < 8; j++) c[i][j] = 0.f;

#pragma unroll 2
        for (int d = 0; d < DD; d++) {
            float a[8], bb[8];
            *(float4*)&a[0]  = *(const float4*)&Qs[d * 136 + gy * 8];
            *(float4*)&a[4]  = *(const float4*)&Qs[d * 136 + gy * 8 + 4];
            *(float4*)&bb[0] = *(const float4*)&Ks[d * 136 + gx * 8];
            *(float4*)&bb[4] = *(const float4*)&Ks[d * 136 + gx * 8 + 4];
#pragma unroll
            for (int i = 0; i < 8; i++)
#pragma unroll
                for (int j = 0; j < 8; j++)
                    c[i][j] += a[i] * bb[j];
        }

#pragma unroll
        for (int i = 0; i < 8; i++) {
#pragma unroll
            for (int j = 0; j < 8; j++) c[i][j] *= scale;
            float mx = c[i][0];
#pragma unroll
            for (int j = 1; j < 8; j++) mx = fmaxf(mx, c[i][j]);
#pragma unroll
            for (int o = 1; o < 16; o <<= 1)
                mx = fmaxf(mx, __shfl_xor_sync(0xffffffffu, mx, o));
            float mn  = fmaxf(m_i[i], mx);
            float fac = __expf(m_i[i] - mn);
            float rs  = 0.f;
#pragma unroll
            for (int j = 0; j < 8; j++) {
                c[i][j] = __expf(c[i][j] - mn);
                rs += c[i][j];
            }
#pragma unroll
            for (int o = 1; o < 16; o <<= 1)
                rs += __shfl_xor_sync(0xffffffffu, rs, o);
            l_i[i] = l_i[i] * fac + rs;
            m_i[i] = mn;
#pragma unroll
            for (int j = 0; j < 8; j++) O[i][j] *= fac;
        }

        __syncthreads();
#pragma unroll
        for (int i = 0; i < 8; i++)
#pragma unroll
            for (int j = 0; j < 8; j++)
                Ks[(gx * 8 + j) * 136 + gy * 8 + i] = c[i][j];
        __syncthreads();

#pragma unroll 2
        for (int kk = 0; kk < 128; kk++) {
            float pp[8], vv[8];
            *(float4*)&pp[0] = *(const float4*)&Ks[kk * 136 + gy * 8];
            *(float4*)&pp[4] = *(const float4*)&Ks[kk * 136 + gy * 8 + 4];
            *(float4*)&vv[0] = *(const float4*)&Vs[kk * DD + gx * 8];
            *(float4*)&vv[4] = *(const float4*)&Vs[kk * DD + gx * 8 + 4];
#pragma unroll
            for (int i = 0; i < 8; i++)
#pragma unroll
                for (int j = 0; j < 8; j++)
                    O[i][j] += pp[i] * vv[j];
        }
    }

    // Normalize, split to hi/lo bf16, write ctx [B*S, E]
#pragma unroll
    for (int i = 0; i < 8; i++) {
        float inv = 1.f / l_i[i];
        int s = q0 + gy * 8 + i;
        size_t rowoff = ((size_t)(b * SS + s)) * EE + h * DD + gx * 8;
        __nv_bfloat16 hv[8], lv[8];
#pragma unroll
        for (int j = 0; j < 8; j++) {
            float x = O[i][j] * inv;
            hv[j] = __float2bfloat16_rn(x);
            lv[j] = __float2bfloat16_rn(x - __bfloat162float(hv[j]));
        }
        *(uint4*)&g_ch[rowoff] = *(uint4*)hv;
        *(uint4*)&g_cl[rowoff] = *(uint4*)lv;
    }
}

// ---------------------------------------------------------------------------
// Launch
// ---------------------------------------------------------------------------
extern "C" void kernel_launch(void* const* d_in, const int* in_sizes, int n_in,
                              void* d_out, int out_size)
{
    (void)in_sizes; (void)n_in; (void)out_size;
    const float* x      = (const float*)d_in[0];
    const float* Wqkv_w = (const float*)d_in[1];
    const float* Wqkv_b = (const float*)d_in[2];
    const float* out_w  = (const float*)d_in[3];
    const float* out_b  = (const float*)d_in[4];
    float* out = (float*)d_out;

    __nv_bfloat16 *xh, *xl, *wqh, *wql, *owh, *owl, *ch, *cl;
    cudaGetSymbolAddress((void**)&xh,  g_xh);
    cudaGetSymbolAddress((void**)&xl,  g_xl);
    cudaGetSymbolAddress((void**)&wqh, g_wqh);
    cudaGetSymbolAddress((void**)&wql, g_wql);
    cudaGetSymbolAddress((void**)&owh, g_owh);
    cudaGetSymbolAddress((void**)&owl, g_owl);
    cudaGetSymbolAddress((void**)&ch,  g_ch);
    cudaGetSymbolAddress((void**)&cl,  g_cl);

    cudaFuncSetAttribute(attn_kernel, cudaFuncAttributeMaxDynamicSharedMemorySize,
                         ATT_SMEM_FLOATS * (int)sizeof(float));
    cudaFuncSetAttribute(gemm_mma<0>, cudaFuncAttributeMaxDynamicSharedMemorySize,
                         GEMM_SMEM);
    cudaFuncSetAttribute(gemm_mma<1>, cudaFuncAttributeMaxDynamicSharedMemorySize,
                         GEMM_SMEM);

    rope_table_kernel<<<(SS * 64 + 255) / 256, 256>>>();

    split_kernel<<<(MTOT*KDIM/4 + 255) / 256, 256>>>(x, xh, xl, MTOT*KDIM);
    split_kernel<<<(NQKV*KDIM/4 + 255) / 256, 256>>>(Wqkv_w, wqh, wql, NQKV*KDIM);
    split_kernel<<<(EE*KDIM/4 + 255) / 256, 256>>>(out_w, owh, owl, EE*KDIM);

    gemm_mma<0><<<dim3(NQKV/128, MTOT/128), 256, GEMM_SMEM>>>(
        xh, xl, wqh, wql, Wqkv_b, nullptr, MTOT, NQKV, KDIM);

    rope_apply_kernel<<<(2 * BB * HH * SS * 64) / 256, 256>>>();

    attn_kernel<<<dim3(SS/128, HH, BB), 256, ATT_SMEM_FLOATS * sizeof(float)>>>();

    gemm_mma<1><<<dim3(EE/128, MTOT/128), 256, GEMM_SMEM>>>(
        ch, cl, owh, owl, out_b, out, MTOT, EE, KDIM);
}

// round 6
// speedup vs baseline: 2.3436x; 1.6960x over previous
#include <cuda_runtime.h>
#include <cuda_bf16.h>
#include <math.h>
#include <stdint.h>

// Problem constants
#define BB   2
#define SS   2048
#define EE   2048
#define HH   16
#define DD   128
#define MTOT (BB*SS)      // 4096
#define NQKV (3*EE)       // 6144
#define KDIM EE           // 2048

// ---------------------------------------------------------------------------
// Scratch (device globals; no allocation allowed)
// ---------------------------------------------------------------------------
__device__ float g_q[(size_t)BB*HH*SS*DD];     // fp32 (pre-RoPE)
__device__ float g_k[(size_t)BB*HH*SS*DD];
__device__ float g_cos[SS*64];
__device__ float g_sin[SS*64];

__device__ __nv_bfloat16 g_qh[(size_t)BB*HH*SS*DD];
__device__ __nv_bfloat16 g_ql[(size_t)BB*HH*SS*DD];
__device__ __nv_bfloat16 g_kh[(size_t)BB*HH*SS*DD];
__device__ __nv_bfloat16 g_kl[(size_t)BB*HH*SS*DD];
__device__ __nv_bfloat16 g_vh[(size_t)BB*HH*SS*DD];
__device__ __nv_bfloat16 g_vl[(size_t)BB*HH*SS*DD];

__device__ __nv_bfloat16 g_xh[(size_t)MTOT*KDIM];
__device__ __nv_bfloat16 g_xl[(size_t)MTOT*KDIM];
__device__ __nv_bfloat16 g_wqh[(size_t)NQKV*KDIM];
__device__ __nv_bfloat16 g_wql[(size_t)NQKV*KDIM];
__device__ __nv_bfloat16 g_owh[(size_t)EE*KDIM];
__device__ __nv_bfloat16 g_owl[(size_t)EE*KDIM];
__device__ __nv_bfloat16 g_ch[(size_t)MTOT*EE];
__device__ __nv_bfloat16 g_cl[(size_t)MTOT*EE];

// ---------------------------------------------------------------------------
// Baseline-PTX helpers (sm_80+)
// ---------------------------------------------------------------------------
__device__ __forceinline__ uint32_t smem_u32(const void* p) {
    uint32_t a;
    asm("{ .reg .u64 t; cvta.to.shared.u64 t, %1; cvt.u32.u64 %0, t; }"
        : "=r"(a) : "l"(p));
    return a;
}

#define CP_ASYNC16(dst, src) \
    asm volatile("cp.async.cg.shared.global [%0], [%1], 16;" \
                 :: "r"(dst), "l"(src) : "memory")
#define CP_COMMIT() asm volatile("cp.async.commit_group;" ::: "memory")

__device__ __forceinline__ void ldmatrix_x4(uint32_t* r, uint32_t addr) {
    asm volatile("ldmatrix.sync.aligned.m8n8.x4.shared.b16 {%0,%1,%2,%3}, [%4];"
                 : "=r"(r[0]), "=r"(r[1]), "=r"(r[2]), "=r"(r[3]) : "r"(addr));
}
__device__ __forceinline__ void ldmatrix_x4_t(uint32_t* r, uint32_t addr) {
    asm volatile("ldmatrix.sync.aligned.m8n8.x4.trans.shared.b16 {%0,%1,%2,%3}, [%4];"
                 : "=r"(r[0]), "=r"(r[1]), "=r"(r[2]), "=r"(r[3]) : "r"(addr));
}

__device__ __forceinline__ void mma16816(float* c,
    uint32_t a0, uint32_t a1, uint32_t a2, uint32_t a3, uint32_t b0, uint32_t b1)
{
    asm volatile(
        "mma.sync.aligned.m16n8k16.row.col.f32.bf16.bf16.f32 "
        "{%0,%1,%2,%3}, {%4,%5,%6,%7}, {%8,%9}, {%0,%1,%2,%3};"
        : "+f"(c[0]), "+f"(c[1]), "+f"(c[2]), "+f"(c[3])
        : "r"(a0), "r"(a1), "r"(a2), "r"(a3), "r"(b0), "r"(b1));
}

__device__ __forceinline__ void split1(float x, __nv_bfloat16& h, __nv_bfloat16& l) {
    h = __float2bfloat16_rn(x);
    l = __float2bfloat16_rn(x - __bfloat162float(h));
}
__device__ __forceinline__ void pack_split(float x, float y,
                                           uint32_t& hi, uint32_t& lo) {
    __nv_bfloat16 hx, lx, hy, ly;
    split1(x, hx, lx); split1(y, hy, ly);
    uint16_t a = *(uint16_t*)&hx, b = *(uint16_t*)&hy;
    uint16_t c = *(uint16_t*)&lx, d = *(uint16_t*)&ly;
    hi = (uint32_t)a | ((uint32_t)b << 16);
    lo = (uint32_t)c | ((uint32_t)d << 16);
}

// ---------------------------------------------------------------------------
// fp32 -> (hi, lo) bf16 split (bulk)
// ---------------------------------------------------------------------------
__global__ void split_kernel(const float* __restrict__ src,
                             __nv_bfloat16* __restrict__ hi,
                             __nv_bfloat16* __restrict__ lo, int n)
{
    int i4 = (blockIdx.x * blockDim.x + threadIdx.x) << 2;
    if (i4 >= n) return;
    float4 v = *(const float4*)(src + i4);
    float xs[4] = {v.x, v.y, v.z, v.w};
    __nv_bfloat16 h[4], l[4];
#pragma unroll
    for (int q = 0; q < 4; q++) split1(xs[q], h[q], l[q]);
    *(uint2*)(hi + i4) = *(uint2*)h;
    *(uint2*)(lo + i4) = *(uint2*)l;
}

// ---------------------------------------------------------------------------
// RoPE table
// ---------------------------------------------------------------------------
__global__ void rope_table_kernel()
{
    int idx = blockIdx.x * blockDim.x + threadIdx.x;
    if (idx >= SS * 64) return;
    int j = idx & 63;
    int s = idx >> 6;
    double denom = pow(10000.0, ((double)(2 * j)) / 128.0);
    float invf = (float)(1.0 / denom);
    float ph = (float)s * invf;
    double p = (double)ph;
    g_cos[idx] = (float)cos(p);
    g_sin[idx] = (float)sin(p);
}

// RoPE on fp32 q/k, writing bf16 hi/lo directly
__global__ void rope_split_kernel()
{
    int idx = blockIdx.x * blockDim.x + threadIdx.x;   // 2*65536*64
    int j      = idx & 63;
    int r      = idx >> 6;
    int bhs    = r & (BB*HH*SS - 1);
    int tensor = r >> 16;
    int s      = bhs & (SS - 1);

    const float* src = tensor ? g_k : g_q;
    __nv_bfloat16* dh = tensor ? g_kh : g_qh;
    __nv_bfloat16* dl = tensor ? g_kl : g_ql;
    size_t base = (size_t)bhs * DD;
    float c  = g_cos[(s << 6) + j];
    float sn = g_sin[(s << 6) + j];
    float x1 = src[base + j];
    float x2 = src[base + j + 64];
    float y1 = x1 * c - x2 * sn;
    float y2 = x2 * c + x1 * sn;
    __nv_bfloat16 h, l;
    split1(y1, h, l); dh[base + j] = h;      dl[base + j] = l;
    split1(y2, h, l); dh[base + j + 64] = h; dl[base + j + 64] = l;
}

// ---------------------------------------------------------------------------
// mma.sync bf16x3 GEMM (R3-verified). MODE 0: q,k fp32 + v split bf16.
// MODE 1: C fp32.
// ---------------------------------------------------------------------------
#define GK_CHUNK   32
#define TILE_BYTES 10240
#define STAGE_BYTES (4*TILE_BYTES)
#define GSTAGES    3
#define GEMM_SMEM  (GSTAGES*STAGE_BYTES)

__device__ __forceinline__ void gemm_load_stage(
    uint32_t stg, const __nv_bfloat16* const* tp, int K, int kt, int tid)
{
#pragma unroll
    for (int t = 0; t < 4; t++) {
        const __nv_bfloat16* p = tp[t];
#pragma unroll
        for (int i = 0; i < 2; i++) {
            int slot = tid + (i << 8);
            int row  = slot >> 2;
            int c    = slot & 3;
            uint32_t dst = stg + t * TILE_BYTES + row * 80 + c * 16;
            const void* src = p + (size_t)row * K + kt + c * 8;
            CP_ASYNC16(dst, src);
        }
    }
    CP_COMMIT();
}

template<int MODE>
__global__ __launch_bounds__(256) void gemm_mma(
    const __nv_bfloat16* __restrict__ Ah, const __nv_bfloat16* __restrict__ Al,
    const __nv_bfloat16* __restrict__ Bh, const __nv_bfloat16* __restrict__ Bl,
    const float* __restrict__ bias, float* __restrict__ C,
    int M, int N, int K)
{
    extern __shared__ char smch[];
    const uint32_t sbase = smem_u32(smch);
    const int tid  = threadIdx.x;
    const int wid  = tid >> 5;
    const int lane = tid & 31;
    const int wm   = wid & 1;
    const int wn   = wid >> 1;
    const int m0   = blockIdx.y << 7;
    const int n0   = blockIdx.x << 7;

    const __nv_bfloat16* tp[4] = {
        Ah + (size_t)m0 * K, Al + (size_t)m0 * K,
        Bh + (size_t)n0 * K, Bl + (size_t)n0 * K };

    float c[4][4][4];
#pragma unroll
    for (int i = 0; i < 4; i++)
#pragma unroll
        for (int j = 0; j < 4; j++)
#pragma unroll
            for (int q = 0; q < 4; q++) c[i][j][q] = 0.f;

    const int T = K / GK_CHUNK;

    gemm_load_stage(sbase + 0 * STAGE_BYTES, tp, K, 0 * GK_CHUNK, tid);
    gemm_load_stage(sbase + 1 * STAGE_BYTES, tp, K, 1 * GK_CHUNK, tid);
    gemm_load_stage(sbase + 2 * STAGE_BYTES, tp, K, 2 * GK_CHUNK, tid);

    const int rsel = lane & 15;
    const int csel = (lane >> 4) << 3;

#pragma unroll 1
    for (int t = 0; t < T; t++) {
        int rem = (T - 1) - t;
        if (rem >= 2)      asm volatile("cp.async.wait_group 2;" ::: "memory");
        else if (rem == 1) asm volatile("cp.async.wait_group 1;" ::: "memory");
        else               asm volatile("cp.async.wait_group 0;" ::: "memory");
        __syncthreads();

        const uint32_t stg = sbase + (t % GSTAGES) * STAGE_BYTES;
        const uint32_t aA[3] = { stg, stg + TILE_BYTES, stg };
        const uint32_t aB[3] = { stg + 2*TILE_BYTES, stg + 2*TILE_BYTES,
                                 stg + 3*TILE_BYTES };

#pragma unroll
        for (int p = 0; p < 3; p++) {
#pragma unroll
            for (int k16 = 0; k16 < 2; k16++) {
                uint32_t a[4][4], b[2][4];
#pragma unroll
                for (int i = 0; i < 4; i++)
                    ldmatrix_x4(a[i], aA[p] + (wm*64 + i*16 + rsel)*80
                                       + (csel + k16*16)*2);
#pragma unroll
                for (int j16 = 0; j16 < 2; j16++)
                    ldmatrix_x4(b[j16], aB[p] + (wn*32 + j16*16 + rsel)*80
                                         + (csel + k16*16)*2);
#pragma unroll
                for (int i = 0; i < 4; i++)
#pragma unroll
                    for (int j16 = 0; j16 < 2; j16++) {
                        mma16816(c[i][j16*2+0], a[i][0], a[i][1], a[i][2], a[i][3],
                                 b[j16][0], b[j16][2]);
                        mma16816(c[i][j16*2+1], a[i][0], a[i][1], a[i][2], a[i][3],
                                 b[j16][1], b[j16][3]);
                    }
            }
        }
        __syncthreads();
        if (t + 3 < T)
            gemm_load_stage(sbase + ((t+3) % GSTAGES) * STAGE_BYTES,
                            tp, K, (t+3) * GK_CHUNK, tid);
    }

#pragma unroll
    for (int i = 0; i < 4; i++) {
        int rowA = m0 + wm*64 + i*16 + (lane >> 2);
#pragma unroll
        for (int j = 0; j < 4; j++) {
            int col = n0 + wn*32 + j*8 + (lane & 3)*2;
            float b0 = bias[col], b1 = bias[col+1];
            float2 lo2 = make_float2(c[i][j][0] + b0, c[i][j][1] + b1);
            float2 hi2 = make_float2(c[i][j][2] + b0, c[i][j][3] + b1);
#pragma unroll
            for (int half = 0; half < 2; half++) {
                int row = rowA + half*8;
                float2 v = half ? hi2 : lo2;
                if (MODE == 0) {
                    int which = col >> 11;
                    int h = (col >> 7) & (HH - 1);
                    int d = col & (DD - 1);
                    int bb = row >> 11;
                    int s = row & (SS - 1);
                    size_t off = (((size_t)bb * HH + h) * SS + s) * DD + d;
                    if (which == 2) {
                        __nv_bfloat16 h0, l0, h1, l1;
                        split1(v.x, h0, l0); split1(v.y, h1, l1);
                        __nv_bfloat162 hp = __halves2bfloat162(h0, h1);
                        __nv_bfloat162 lp = __halves2bfloat162(l0, l1);
                        *(__nv_bfloat162*)&g_vh[off] = hp;
                        *(__nv_bfloat162*)&g_vl[off] = lp;
                    } else {
                        float* dst = which ? g_k : g_q;
                        *(float2*)&dst[off] = v;
                    }
                } else {
                    *(float2*)&C[(size_t)row * N + col] = v;
                }
            }
        }
    }
}

// ---------------------------------------------------------------------------
// Tensor-core flash attention (bf16x3 split on QK^T and PV).
// CTA = 128 q rows x (b,h). 8 warps x 16 q rows. K/V tiles of 64 keys,
// SINGLE-buffered, split-phase pipelined:
//   K(t+1) issued right after QK^T(t) (K buffer dead), overlaps softmax+PV(t);
//   V(t+1) issued right after PV(t)  (V buffer dead), overlaps QK^T(t+1).
// Commit order alternates K,V,K,V...; wait_group 1 always drains the oldest.
// ---------------------------------------------------------------------------
#define AT_ROWB  272                    // 136 bf16 per row
#define Q_BYTES  (128*AT_ROWB)          // 34816
#define KV_TILE  (64*AT_ROWB)           // 17408
#define ATT_SMEM (2*Q_BYTES + 4*KV_TILE)  // 139264

__global__ __launch_bounds__(256, 1) void attn_mma_kernel()
{
    extern __shared__ char smc[];
    const uint32_t sb  = smem_u32(smc);
    const uint32_t sQh = sb;
    const uint32_t sQl = sb + Q_BYTES;
    const uint32_t sKh = sb + 2*Q_BYTES;
    const uint32_t sKl = sKh + KV_TILE;
    const uint32_t sVh = sKl + KV_TILE;
    const uint32_t sVl = sVh + KV_TILE;

    const int tid  = threadIdx.x;
    const int wid  = tid >> 5;
    const int lane = tid & 31;
    const int q0 = blockIdx.x << 7;
    const int h  = blockIdx.y;
    const int b  = blockIdx.z;

    const size_t head_off = ((size_t)b * HH + h) * SS * DD;
    const __nv_bfloat16* Qhg = g_qh + head_off + (size_t)q0 * DD;
    const __nv_bfloat16* Qlg = g_ql + head_off + (size_t)q0 * DD;
    const __nv_bfloat16* Khg = g_kh + head_off;
    const __nv_bfloat16* Klg = g_kl + head_off;
    const __nv_bfloat16* Vhg = g_vh + head_off;
    const __nv_bfloat16* Vlg = g_vl + head_off;

    // K tile loader: 2 arrays x 64 rows x 16 chunks = 2048 cp.asyncs (8/thread)
    auto load_k = [&](int kt) {
#pragma unroll
        for (int i = 0; i < 8; i++) {
            int idx = tid + (i << 8);
            int arr = idx >> 10;
            int row = (idx >> 4) & 63;
            int c   = idx & 15;
            const __nv_bfloat16* src = arr ? Klg : Khg;
            uint32_t dstb = arr ? sKl : sKh;
            CP_ASYNC16(dstb + row*AT_ROWB + c*16, src + (size_t)(kt+row)*DD + c*8);
        }
        CP_COMMIT();
    };
    auto load_v = [&](int kt) {
#pragma unroll
        for (int i = 0; i < 8; i++) {
            int idx = tid + (i << 8);
            int arr = idx >> 10;
            int row = (idx >> 4) & 63;
            int c   = idx & 15;
            const __nv_bfloat16* src = arr ? Vlg : Vhg;
            uint32_t dstb = arr ? sVl : sVh;
            CP_ASYNC16(dstb + row*AT_ROWB + c*16, src + (size_t)(kt+row)*DD + c*8);
        }
        CP_COMMIT();
    };

    // ---- prologue: Q (both halves) + K0 + V0, one commit group ----
    {
#pragma unroll
        for (int i = 0; i < 8; i++) {
            int cidx = tid + (i << 8);         // 0..2047
            int row = cidx >> 4, c = cidx & 15;
            CP_ASYNC16(sQh + row*AT_ROWB + c*16, Qhg + (size_t)row*DD + c*8);
            CP_ASYNC16(sQl + row*AT_ROWB + c*16, Qlg + (size_t)row*DD + c*8);
        }
#pragma unroll
        for (int i = 0; i < 16; i++) {
            int idx = tid + (i << 8);          // 0..4095: Kh,Kl,Vh,Vl tiles
            int arr = idx >> 10;               // 0..3
            int row = (idx >> 4) & 63;
            int c   = idx & 15;
            const __nv_bfloat16* srcs[4] = { Khg, Klg, Vhg, Vlg };
            uint32_t dsts[4] = { sKh, sKl, sVh, sVl };
            CP_ASYNC16(dsts[arr] + row*AT_ROWB + c*16,
                       srcs[arr] + (size_t)row*DD + c*8);
        }
        CP_COMMIT();
    }

    float o[16][4];
#pragma unroll
    for (int n = 0; n < 16; n++)
#pragma unroll
        for (int q = 0; q < 4; q++) o[n][q] = 0.f;
    float m0 = -1e30f, m1 = -1e30f, l0 = 0.f, l1 = 0.f;

    const float scale = 0.088388347648318447f;   // 1/sqrt(128)
    const int wq = wid << 4;
    const int rsel = lane & 15;
    const int csel = (lane >> 4) << 3;
    const int NT = SS / 64;                      // 32

#pragma unroll 1
    for (int t = 0; t < NT; t++) {
        // ---- K(t) ready? ----
        if (t == 0) asm volatile("cp.async.wait_group 0;" ::: "memory");
        else        asm volatile("cp.async.wait_group 1;" ::: "memory");
        __syncthreads();

        // ---- scores S = QK^T (3 products) ----
        float S[8][4];
#pragma unroll
        for (int j = 0; j < 8; j++)
#pragma unroll
            for (int q = 0; q < 4; q++) S[j][q] = 0.f;

#pragma unroll
        for (int ds = 0; ds < 8; ds++) {
            const int doff = (ds*16 + csel) * 2;
            uint32_t qh[4], ql[4], kh[4][4], kl[4][4];
            ldmatrix_x4(qh, sQh + (wq + rsel)*AT_ROWB + doff);
            ldmatrix_x4(ql, sQl + (wq + rsel)*AT_ROWB + doff);
#pragma unroll
            for (int j16 = 0; j16 < 4; j16++) {
                ldmatrix_x4(kh[j16], sKh + (j16*16 + rsel)*AT_ROWB + doff);
                ldmatrix_x4(kl[j16], sKl + (j16*16 + rsel)*AT_ROWB + doff);
            }
#pragma unroll
            for (int j16 = 0; j16 < 4; j16++) {
                mma16816(S[2*j16],   qh[0], qh[1], qh[2], qh[3], kh[j16][0], kh[j16][2]);
                mma16816(S[2*j16+1], qh[0], qh[1], qh[2], qh[3], kh[j16][1], kh[j16][3]);
            }
#pragma unroll
            for (int j16 = 0; j16 < 4; j16++) {
                mma16816(S[2*j16],   ql[0], ql[1], ql[2], ql[3], kh[j16][0], kh[j16][2]);
                mma16816(S[2*j16+1], ql[0], ql[1], ql[2], ql[3], kh[j16][1], kh[j16][3]);
            }
#pragma unroll
            for (int j16 = 0; j16 < 4; j16++) {
                mma16816(S[2*j16],   qh[0], qh[1], qh[2], qh[3], kl[j16][0], kl[j16][2]);
                mma16816(S[2*j16+1], qh[0], qh[1], qh[2], qh[3], kl[j16][1], kl[j16][3]);
            }
        }
        __syncthreads();                 // all warps done reading K tile

        // K buffer dead -> start K(t+1); overlaps softmax + PV below
        if (t + 1 < NT) load_k((t + 1) << 6);

        // ---- online softmax ----
        float mx0 = -1e30f, mx1 = -1e30f;
#pragma unroll
        for (int j = 0; j < 8; j++) {
            S[j][0] *= scale; S[j][1] *= scale;
            S[j][2] *= scale; S[j][3] *= scale;
            mx0 = fmaxf(mx0, fmaxf(S[j][0], S[j][1]));
            mx1 = fmaxf(mx1, fmaxf(S[j][2], S[j][3]));
        }
        mx0 = fmaxf(mx0, __shfl_xor_sync(0xffffffffu, mx0, 1));
        mx0 = fmaxf(mx0, __shfl_xor_sync(0xffffffffu, mx0, 2));
        mx1 = fmaxf(mx1, __shfl_xor_sync(0xffffffffu, mx1, 1));
        mx1 = fmaxf(mx1, __shfl_xor_sync(0xffffffffu, mx1, 2));

        float mn0 = fmaxf(m0, mx0), mn1 = fmaxf(m1, mx1);
        float fac0 = __expf(m0 - mn0), fac1 = __expf(m1 - mn1);
        float rs0 = 0.f, rs1 = 0.f;
#pragma unroll
        for (int j = 0; j < 8; j++) {
            S[j][0] = __expf(S[j][0] - mn0); rs0 += S[j][0];
            S[j][1] = __expf(S[j][1] - mn0); rs0 += S[j][1];
            S[j][2] = __expf(S[j][2] - mn1); rs1 += S[j][2];
            S[j][3] = __expf(S[j][3] - mn1); rs1 += S[j][3];
        }
        rs0 += __shfl_xor_sync(0xffffffffu, rs0, 1);
        rs0 += __shfl_xor_sync(0xffffffffu, rs0, 2);
        rs1 += __shfl_xor_sync(0xffffffffu, rs1, 1);
        rs1 += __shfl_xor_sync(0xffffffffu, rs1, 2);
        l0 = l0 * fac0 + rs0; m0 = mn0;
        l1 = l1 * fac1 + rs1; m1 = mn1;
#pragma unroll
        for (int n = 0; n < 16; n++) {
            o[n][0] *= fac0; o[n][1] *= fac0;
            o[n][2] *= fac1; o[n][3] *= fac1;
        }

        // ---- V(t) ready? (oldest pending group; K(t+1) may still be in flight)
        if (t + 1 < NT) asm volatile("cp.async.wait_group 1;" ::: "memory");
        else            asm volatile("cp.async.wait_group 0;" ::: "memory");
        __syncthreads();

        // ---- O += P V (3 products); P from registers ----
#pragma unroll
        for (int kk = 0; kk < 4; kk++) {
            uint32_t ah[4], al[4];
            pack_split(S[2*kk][0],   S[2*kk][1],   ah[0], al[0]);
            pack_split(S[2*kk][2],   S[2*kk][3],   ah[1], al[1]);
            pack_split(S[2*kk+1][0], S[2*kk+1][1], ah[2], al[2]);
            pack_split(S[2*kk+1][2], S[2*kk+1][3], ah[3], al[3]);
            const uint32_t vrow = (kk*16 + rsel)*AT_ROWB;
#pragma unroll
            for (int db = 0; db < 8; db += 2) {
                uint32_t vh[2][4], vl[2][4];
                ldmatrix_x4_t(vh[0], sVh + vrow + (db*16 + csel)*2);
                ldmatrix_x4_t(vl[0], sVl + vrow + (db*16 + csel)*2);
                ldmatrix_x4_t(vh[1], sVh + vrow + ((db+1)*16 + csel)*2);
                ldmatrix_x4_t(vl[1], sVl + vrow + ((db+1)*16 + csel)*2);
#pragma unroll
                for (int u = 0; u < 2; u++) {
                    int n = (db+u)*2;
                    mma16816(o[n],   ah[0], ah[1], ah[2], ah[3], vh[u][0], vh[u][1]);
                    mma16816(o[n+1], ah[0], ah[1], ah[2], ah[3], vh[u][2], vh[u][3]);
                }
#pragma unroll
                for (int u = 0; u < 2; u++) {
                    int n = (db+u)*2;
                    mma16816(o[n],   al[0], al[1], al[2], al[3], vh[u][0], vh[u][1]);
                    mma16816(o[n+1], al[0], al[1], al[2], al[3], vh[u][2], vh[u][3]);
                }
#pragma unroll
                for (int u = 0; u < 2; u++) {
                    int n = (db+u)*2;
                    mma16816(o[n],   ah[0], ah[1], ah[2], ah[3], vl[u][0], vl[u][1]);
                    mma16816(o[n+1], ah[0], ah[1], ah[2], ah[3], vl[u][2], vl[u][3]);
                }
            }
        }
        __syncthreads();                 // all warps done reading V tile

        // V buffer dead -> start V(t+1); overlaps next QK^T
        if (t + 1 < NT) load_v((t + 1) << 6);
    }

    // ---- epilogue: normalize, split to hi/lo bf16, write ctx ----
    const int g  = lane >> 2;
    const int tg = lane & 3;
    const float inv0 = 1.f / l0;
    const float inv1 = 1.f / l1;
    const int s0 = q0 + wq + g;
    const int s1 = s0 + 8;
#pragma unroll
    for (int n = 0; n < 16; n++) {
        int col = h*DD + 8*n + 2*tg;
        {
            size_t off = (size_t)(b*SS + s0) * EE + col;
            __nv_bfloat16 h0, l0b, h1, l1b;
            split1(o[n][0] * inv0, h0, l0b);
            split1(o[n][1] * inv0, h1, l1b);
            *(__nv_bfloat162*)&g_ch[off] = __halves2bfloat162(h0, h1);
            *(__nv_bfloat162*)&g_cl[off] = __halves2bfloat162(l0b, l1b);
        }
        {
            size_t off = (size_t)(b*SS + s1) * EE + col;
            __nv_bfloat16 h0, l0b, h1, l1b;
            split1(o[n][2] * inv1, h0, l0b);
            split1(o[n][3] * inv1, h1, l1b);
            *(__nv_bfloat162*)&g_ch[off] = __halves2bfloat162(h0, h1);
            *(__nv_bfloat162*)&g_cl[off] = __halves2bfloat162(l0b, l1b);
        }
    }
}

// ---------------------------------------------------------------------------
// Launch
// ---------------------------------------------------------------------------
extern "C" void kernel_launch(void* const* d_in, const int* in_sizes, int n_in,
                              void* d_out, int out_size)
{
    (void)in_sizes; (void)n_in; (void)out_size;
    const float* x      = (const float*)d_in[0];
    const float* Wqkv_w = (const float*)d_in[1];
    const float* Wqkv_b = (const float*)d_in[2];
    const float* out_w  = (const float*)d_in[3];
    const float* out_b  = (const float*)d_in[4];
    float* out = (float*)d_out;

    __nv_bfloat16 *xh, *xl, *wqh, *wql, *owh, *owl, *ch, *cl;
    cudaGetSymbolAddress((void**)&xh,  g_xh);
    cudaGetSymbolAddress((void**)&xl,  g_xl);
    cudaGetSymbolAddress((void**)&wqh, g_wqh);
    cudaGetSymbolAddress((void**)&wql, g_wql);
    cudaGetSymbolAddress((void**)&owh, g_owh);
    cudaGetSymbolAddress((void**)&owl, g_owl);
    cudaGetSymbolAddress((void**)&ch,  g_ch);
    cudaGetSymbolAddress((void**)&cl,  g_cl);

    cudaFuncSetAttribute(attn_mma_kernel, cudaFuncAttributeMaxDynamicSharedMemorySize,
                         ATT_SMEM);
    cudaFuncSetAttribute(gemm_mma<0>, cudaFuncAttributeMaxDynamicSharedMemorySize,
                         GEMM_SMEM);
    cudaFuncSetAttribute(gemm_mma<1>, cudaFuncAttributeMaxDynamicSharedMemorySize,
                         GEMM_SMEM);

    rope_table_kernel<<<(SS * 64 + 255) / 256, 256>>>();

    split_kernel<<<(MTOT*KDIM/4 + 255) / 256, 256>>>(x, xh, xl, MTOT*KDIM);
    split_kernel<<<(NQKV*KDIM/4 + 255) / 256, 256>>>(Wqkv_w, wqh, wql, NQKV*KDIM);
    split_kernel<<<(EE*KDIM/4 + 255) / 256, 256>>>(out_w, owh, owl, EE*KDIM);

    gemm_mma<0><<<dim3(NQKV/128, MTOT/128), 256, GEMM_SMEM>>>(
        xh, xl, wqh, wql, Wqkv_b, nullptr, MTOT, NQKV, KDIM);

    rope_split_kernel<<<(2 * BB * HH * SS * 64) / 256, 256>>>();

    attn_mma_kernel<<<dim3(SS/128, HH, BB), 256, ATT_SMEM>>>();

    gemm_mma<1><<<dim3(EE/128, MTOT/128), 256, GEMM_SMEM>>>(
        ch, cl, owh, owl, out_b, out, MTOT, EE, KDIM);
}

// round 8
// speedup vs baseline: 3.6403x; 1.5533x over previous
#include <cuda_runtime.h>
#include <cuda_fp16.h>
#include <math.h>
#include <stdint.h>

// Problem constants
#define BB   2
#define SS   2048
#define EE   2048
#define HH   16
#define DD   128
#define MTOT (BB*SS)      // 4096
#define NQKV (3*EE)       // 6144
#define KDIM EE           // 2048

// ---------------------------------------------------------------------------
// Scratch (device globals; no allocation allowed)
// ---------------------------------------------------------------------------
__device__ float g_q[(size_t)BB*HH*SS*DD];     // fp32 (pre-RoPE)
__device__ float g_k[(size_t)BB*HH*SS*DD];
__device__ float g_cos[SS*64];
__device__ float g_sin[SS*64];

__device__ __half g_qh[(size_t)BB*HH*SS*DD];   // RoPE'd Q hi
__device__ __half g_ql[(size_t)BB*HH*SS*DD];   // RoPE'd Q lo
__device__ __half g_kh[(size_t)BB*HH*SS*DD];   // RoPE'd K (single-rounded)
__device__ __half g_vh[(size_t)BB*HH*SS*DD];   // V (single-rounded)

__device__ __half g_xh[(size_t)MTOT*KDIM];     // x hi
__device__ __half g_xl[(size_t)MTOT*KDIM];     // x lo
__device__ __half g_wqh[(size_t)NQKV*KDIM];    // Wqkv (single-rounded)
__device__ __half g_owh[(size_t)EE*KDIM];      // out_w (single-rounded)
__device__ __half g_ch[(size_t)MTOT*EE];       // ctx hi
__device__ __half g_cl[(size_t)MTOT*EE];       // ctx lo

// ---------------------------------------------------------------------------
// Baseline-PTX helpers (sm_80+)
// ---------------------------------------------------------------------------
__device__ __forceinline__ uint32_t smem_u32(const void* p) {
    uint32_t a;
    asm("{ .reg .u64 t; cvta.to.shared.u64 t, %1; cvt.u32.u64 %0, t; }"
        : "=r"(a) : "l"(p));
    return a;
}

#define CP_ASYNC16(dst, src) \
    asm volatile("cp.async.cg.shared.global [%0], [%1], 16;" \
                 :: "r"(dst), "l"(src) : "memory")
#define CP_COMMIT() asm volatile("cp.async.commit_group;" ::: "memory")

__device__ __forceinline__ void ldmatrix_x4(uint32_t* r, uint32_t addr) {
    asm volatile("ldmatrix.sync.aligned.m8n8.x4.shared.b16 {%0,%1,%2,%3}, [%4];"
                 : "=r"(r[0]), "=r"(r[1]), "=r"(r[2]), "=r"(r[3]) : "r"(addr));
}
__device__ __forceinline__ void ldmatrix_x4_t(uint32_t* r, uint32_t addr) {
    asm volatile("ldmatrix.sync.aligned.m8n8.x4.trans.shared.b16 {%0,%1,%2,%3}, [%4];"
                 : "=r"(r[0]), "=r"(r[1]), "=r"(r[2]), "=r"(r[3]) : "r"(addr));
}

// fp16 inputs, fp32 accumulate
__device__ __forceinline__ void mma16816(float* c,
    uint32_t a0, uint32_t a1, uint32_t a2, uint32_t a3, uint32_t b0, uint32_t b1)
{
    asm volatile(
        "mma.sync.aligned.m16n8k16.row.col.f32.f16.f16.f32 "
        "{%0,%1,%2,%3}, {%4,%5,%6,%7}, {%8,%9}, {%0,%1,%2,%3};"
        : "+f"(c[0]), "+f"(c[1]), "+f"(c[2]), "+f"(c[3])
        : "r"(a0), "r"(a1), "r"(a2), "r"(a3), "r"(b0), "r"(b1));
}

__device__ __forceinline__ void split1(float x, __half& h, __half& l) {
    h = __float2half_rn(x);
    l = __float2half_rn(x - __half2float(h));
}
__device__ __forceinline__ void pack_split(float x, float y,
                                           uint32_t& hi, uint32_t& lo) {
    __half hx, lx, hy, ly;
    split1(x, hx, lx); split1(y, hy, ly);
    __half2 hp = __halves2half2(hx, hy);
    __half2 lp = __halves2half2(lx, ly);
    hi = *(uint32_t*)&hp;
    lo = *(uint32_t*)&lp;
}

// ---------------------------------------------------------------------------
// fp32 -> (hi, lo) fp16 split (bulk) and hi-only convert
// ---------------------------------------------------------------------------
__global__ void split_kernel(const float* __restrict__ src,
                             __half* __restrict__ hi,
                             __half* __restrict__ lo, int n)
{
    int i4 = (blockIdx.x * blockDim.x + threadIdx.x) << 2;
    if (i4 >= n) return;
    float4 v = *(const float4*)(src + i4);
    float xs[4] = {v.x, v.y, v.z, v.w};
    __half h[4], l[4];
#pragma unroll
    for (int q = 0; q < 4; q++) split1(xs[q], h[q], l[q]);
    *(uint2*)(hi + i4) = *(uint2*)h;
    *(uint2*)(lo + i4) = *(uint2*)l;
}

__global__ void cvt_hi_kernel(const float* __restrict__ src,
                              __half* __restrict__ hi, int n)
{
    int i4 = (blockIdx.x * blockDim.x + threadIdx.x) << 2;
    if (i4 >= n) return;
    float4 v = *(const float4*)(src + i4);
    __half h[4];
    h[0] = __float2half_rn(v.x); h[1] = __float2half_rn(v.y);
    h[2] = __float2half_rn(v.z); h[3] = __float2half_rn(v.w);
    *(uint2*)(hi + i4) = *(uint2*)h;
}

// ---------------------------------------------------------------------------
// RoPE table
// ---------------------------------------------------------------------------
__global__ void rope_table_kernel()
{
    int idx = blockIdx.x * blockDim.x + threadIdx.x;
    if (idx >= SS * 64) return;
    int j = idx & 63;
    int s = idx >> 6;
    double denom = pow(10000.0, ((double)(2 * j)) / 128.0);
    float invf = (float)(1.0 / denom);
    float ph = (float)s * invf;
    double p = (double)ph;
    g_cos[idx] = (float)cos(p);
    g_sin[idx] = (float)sin(p);
}

// RoPE on fp32 q/k. Q -> (hi, lo) fp16 split; K -> single-rounded fp16.
__global__ void rope_split_kernel()
{
    int idx = blockIdx.x * blockDim.x + threadIdx.x;   // 2*65536*64
    int j      = idx & 63;
    int r      = idx >> 6;
    int bhs    = r & (BB*HH*SS - 1);
    int tensor = r >> 16;
    int s      = bhs & (SS - 1);

    size_t base = (size_t)bhs * DD;
    float c  = g_cos[(s << 6) + j];
    float sn = g_sin[(s << 6) + j];
    if (tensor == 0) {
        float x1 = g_q[base + j];
        float x2 = g_q[base + j + 64];
        float y1 = x1 * c - x2 * sn;
        float y2 = x2 * c + x1 * sn;
        __half h, l;
        split1(y1, h, l); g_qh[base + j] = h;      g_ql[base + j] = l;
        split1(y2, h, l); g_qh[base + j + 64] = h; g_ql[base + j + 64] = l;
    } else {
        float x1 = g_k[base + j];
        float x2 = g_k[base + j + 64];
        float y1 = x1 * c - x2 * sn;
        float y2 = x2 * c + x1 * sn;
        g_kh[base + j]      = __float2half_rn(y1);
        g_kh[base + j + 64] = __float2half_rn(y2);
    }
}

// ---------------------------------------------------------------------------
// mma.sync fp16x2 GEMM: C = Ah*Bh + Al*Bh + bias  (A split, B single-rounded)
// Tile: CTA 128x128, warp 64x32, K-chunk 32, 3-stage cp.async pipeline.
// MODE 0: q,k fp32 + v fp16. MODE 1: C fp32.
// ---------------------------------------------------------------------------
#define GK_CHUNK   32
#define TILE_BYTES 10240            // 128 rows * 80B (32 fp16 + 8 pad)
#define STAGE_BYTES (3*TILE_BYTES)  // Ah, Al, Bh
#define GSTAGES    3
#define GEMM_SMEM  (GSTAGES*STAGE_BYTES)   // 92160 B

__device__ __forceinline__ void gemm_load_stage(
    uint32_t stg, const __half* const* tp, int K, int kt, int tid)
{
#pragma unroll
    for (int t = 0; t < 3; t++) {
        const __half* p = tp[t];
#pragma unroll
        for (int i = 0; i < 2; i++) {
            int slot = tid + (i << 8);
            int row  = slot >> 2;
            int c    = slot & 3;
            uint32_t dst = stg + t * TILE_BYTES + row * 80 + c * 16;
            const void* src = p + (size_t)row * K + kt + c * 8;
            CP_ASYNC16(dst, src);
        }
    }
    CP_COMMIT();
}

template<int MODE>
__global__ __launch_bounds__(256) void gemm_mma(
    const __half* __restrict__ Ah, const __half* __restrict__ Al,
    const __half* __restrict__ Bh,
    const float* __restrict__ bias, float* __restrict__ C,
    int M, int N, int K)
{
    extern __shared__ char smch[];
    const uint32_t sbase = smem_u32(smch);
    const int tid  = threadIdx.x;
    const int wid  = tid >> 5;
    const int lane = tid & 31;
    const int wm   = wid & 1;
    const int wn   = wid >> 1;
    const int m0   = blockIdx.y << 7;
    const int n0   = blockIdx.x << 7;

    const __half* tp[3] = {
        Ah + (size_t)m0 * K, Al + (size_t)m0 * K, Bh + (size_t)n0 * K };

    float c[4][4][4];
#pragma unroll
    for (int i = 0; i < 4; i++)
#pragma unroll
        for (int j = 0; j < 4; j++)
#pragma unroll
            for (int q = 0; q < 4; q++) c[i][j][q] = 0.f;

    const int T = K / GK_CHUNK;

    gemm_load_stage(sbase + 0 * STAGE_BYTES, tp, K, 0 * GK_CHUNK, tid);
    gemm_load_stage(sbase + 1 * STAGE_BYTES, tp, K, 1 * GK_CHUNK, tid);
    gemm_load_stage(sbase + 2 * STAGE_BYTES, tp, K, 2 * GK_CHUNK, tid);

    const int rsel = lane & 15;
    const int csel = (lane >> 4) << 3;

#pragma unroll 1
    for (int t = 0; t < T; t++) {
        int rem = (T - 1) - t;
        if (rem >= 2)      asm volatile("cp.async.wait_group 2;" ::: "memory");
        else if (rem == 1) asm volatile("cp.async.wait_group 1;" ::: "memory");
        else               asm volatile("cp.async.wait_group 0;" ::: "memory");
        __syncthreads();

        const uint32_t stg = sbase + (t % GSTAGES) * STAGE_BYTES;
        const uint32_t aAh = stg;
        const uint32_t aAl = stg + TILE_BYTES;
        const uint32_t aB  = stg + 2*TILE_BYTES;

#pragma unroll
        for (int k16 = 0; k16 < 2; k16++) {
            const int koff = (csel + k16*16)*2;
            uint32_t a0[4][4], a1[4][4], b[2][4];
#pragma unroll
            for (int i = 0; i < 4; i++) {
                ldmatrix_x4(a0[i], aAh + (wm*64 + i*16 + rsel)*80 + koff);
                ldmatrix_x4(a1[i], aAl + (wm*64 + i*16 + rsel)*80 + koff);
            }
#pragma unroll
            for (int j16 = 0; j16 < 2; j16++)
                ldmatrix_x4(b[j16], aB + (wn*32 + j16*16 + rsel)*80 + koff);
#pragma unroll
            for (int i = 0; i < 4; i++)
#pragma unroll
                for (int j16 = 0; j16 < 2; j16++) {
                    mma16816(c[i][j16*2+0], a0[i][0], a0[i][1], a0[i][2], a0[i][3],
                             b[j16][0], b[j16][2]);
                    mma16816(c[i][j16*2+1], a0[i][0], a0[i][1], a0[i][2], a0[i][3],
                             b[j16][1], b[j16][3]);
                }
#pragma unroll
            for (int i = 0; i < 4; i++)
#pragma unroll
                for (int j16 = 0; j16 < 2; j16++) {
                    mma16816(c[i][j16*2+0], a1[i][0], a1[i][1], a1[i][2], a1[i][3],
                             b[j16][0], b[j16][2]);
                    mma16816(c[i][j16*2+1], a1[i][0], a1[i][1], a1[i][2], a1[i][3],
                             b[j16][1], b[j16][3]);
                }
        }
        __syncthreads();
        if (t + 3 < T)
            gemm_load_stage(sbase + ((t+3) % GSTAGES) * STAGE_BYTES,
                            tp, K, (t+3) * GK_CHUNK, tid);
    }

#pragma unroll
    for (int i = 0; i < 4; i++) {
        int rowA = m0 + wm*64 + i*16 + (lane >> 2);
#pragma unroll
        for (int j = 0; j < 4; j++) {
            int col = n0 + wn*32 + j*8 + (lane & 3)*2;
            float b0 = bias[col], b1 = bias[col+1];
            float2 lo2 = make_float2(c[i][j][0] + b0, c[i][j][1] + b1);
            float2 hi2 = make_float2(c[i][j][2] + b0, c[i][j][3] + b1);
#pragma unroll
            for (int half = 0; half < 2; half++) {
                int row = rowA + half*8;
                float2 v = half ? hi2 : lo2;
                if (MODE == 0) {
                    int which = col >> 11;
                    int h = (col >> 7) & (HH - 1);
                    int d = col & (DD - 1);
                    int bb = row >> 11;
                    int s = row & (SS - 1);
                    size_t off = (((size_t)bb * HH + h) * SS + s) * DD + d;
                    if (which == 2) {
                        __half2 hp = __halves2half2(__float2half_rn(v.x),
                                                    __float2half_rn(v.y));
                        *(__half2*)&g_vh[off] = hp;
                    } else {
                        float* dst = which ? g_k : g_q;
                        *(float2*)&dst[off] = v;
                    }
                } else {
                    *(float2*)&C[(size_t)row * N + col] = v;
                }
            }
        }
    }
}

// ---------------------------------------------------------------------------
// Tensor-core flash attention, fp16x2:
//   S = Qh*Kh + Ql*Kh  (Q split, K single-rounded)
//   O += Ph*Vh + Pl*Vh (P split, V single-rounded)
// CTA = 128 q rows x (b,h). 8 warps x 16 q rows. 64-key K/V tiles,
// single-buffered, split-phase pipelined (R6-verified schedule).
// ---------------------------------------------------------------------------
#define AT_ROWB  272                    // 128 fp16 + 8 pad
#define Q_BYTES  (128*AT_ROWB)          // 34816
#define KV_TILE  (64*AT_ROWB)           // 17408
#define ATT_SMEM (2*Q_BYTES + 2*KV_TILE)  // 104448

__global__ __launch_bounds__(256, 1) void attn_mma_kernel()
{
    extern __shared__ char smc[];
    const uint32_t sb  = smem_u32(smc);
    const uint32_t sQh = sb;
    const uint32_t sQl = sb + Q_BYTES;
    const uint32_t sKh = sb + 2*Q_BYTES;
    const uint32_t sVh = sKh + KV_TILE;

    const int tid  = threadIdx.x;
    const int wid  = tid >> 5;
    const int lane = tid & 31;
    const int q0 = blockIdx.x << 7;
    const int h  = blockIdx.y;
    const int b  = blockIdx.z;

    const size_t head_off = ((size_t)b * HH + h) * SS * DD;
    const __half* Qhg = g_qh + head_off + (size_t)q0 * DD;
    const __half* Qlg = g_ql + head_off + (size_t)q0 * DD;
    const __half* Khg = g_kh + head_off;
    const __half* Vhg = g_vh + head_off;

    auto load_k = [&](int kt) {
#pragma unroll
        for (int i = 0; i < 4; i++) {
            int idx = tid + (i << 8);          // 0..1023
            int row = idx >> 4, c = idx & 15;
            CP_ASYNC16(sKh + row*AT_ROWB + c*16, Khg + (size_t)(kt+row)*DD + c*8);
        }
        CP_COMMIT();
    };
    auto load_v = [&](int kt) {
#pragma unroll
        for (int i = 0; i < 4; i++) {
            int idx = tid + (i << 8);
            int row = idx >> 4, c = idx & 15;
            CP_ASYNC16(sVh + row*AT_ROWB + c*16, Vhg + (size_t)(kt+row)*DD + c*8);
        }
        CP_COMMIT();
    };

    // ---- prologue: Q (hi+lo) + K0 + V0, one commit group ----
    {
#pragma unroll
        for (int i = 0; i < 8; i++) {
            int cidx = tid + (i << 8);         // 0..2047
            int row = cidx >> 4, c = cidx & 15;
            CP_ASYNC16(sQh + row*AT_ROWB + c*16, Qhg + (size_t)row*DD + c*8);
            CP_ASYNC16(sQl + row*AT_ROWB + c*16, Qlg + (size_t)row*DD + c*8);
        }
#pragma unroll
        for (int i = 0; i < 8; i++) {
            int idx = tid + (i << 8);          // 0..2047: Kh, Vh tiles
            int arr = idx >> 10;               // 0..1
            int row = (idx >> 4) & 63;
            int c   = idx & 15;
            const __half* src = arr ? Vhg : Khg;
            uint32_t dstb = arr ? sVh : sKh;
            CP_ASYNC16(dstb + row*AT_ROWB + c*16, src + (size_t)row*DD + c*8);
        }
        CP_COMMIT();
    }

    float o[16][4];
#pragma unroll
    for (int n = 0; n < 16; n++)
#pragma unroll
        for (int q = 0; q < 4; q++) o[n][q] = 0.f;
    float m0 = -1e30f, m1 = -1e30f, l0 = 0.f, l1 = 0.f;

    const float scale = 0.088388347648318447f;   // 1/sqrt(128)
    const int wq = wid << 4;
    const int rsel = lane & 15;
    const int csel = (lane >> 4) << 3;
    const int NT = SS / 64;                      // 32

#pragma unroll 1
    for (int t = 0; t < NT; t++) {
        // ---- K(t) ready? ----
        if (t == 0) asm volatile("cp.async.wait_group 0;" ::: "memory");
        else        asm volatile("cp.async.wait_group 1;" ::: "memory");
        __syncthreads();

        // ---- scores S = Qh*Kh + Ql*Kh ----
        float S[8][4];
#pragma unroll
        for (int j = 0; j < 8; j++)
#pragma unroll
            for (int q = 0; q < 4; q++) S[j][q] = 0.f;

#pragma unroll
        for (int ds = 0; ds < 8; ds++) {
            const int doff = (ds*16 + csel) * 2;
            uint32_t qh[4], ql[4], kh[4][4];
            ldmatrix_x4(qh, sQh + (wq + rsel)*AT_ROWB + doff);
            ldmatrix_x4(ql, sQl + (wq + rsel)*AT_ROWB + doff);
#pragma unroll
            for (int j16 = 0; j16 < 4; j16++)
                ldmatrix_x4(kh[j16], sKh + (j16*16 + rsel)*AT_ROWB + doff);
#pragma unroll
            for (int j16 = 0; j16 < 4; j16++) {
                mma16816(S[2*j16],   qh[0], qh[1], qh[2], qh[3], kh[j16][0], kh[j16][2]);
                mma16816(S[2*j16+1], qh[0], qh[1], qh[2], qh[3], kh[j16][1], kh[j16][3]);
            }
#pragma unroll
            for (int j16 = 0; j16 < 4; j16++) {
                mma16816(S[2*j16],   ql[0], ql[1], ql[2], ql[3], kh[j16][0], kh[j16][2]);
                mma16816(S[2*j16+1], ql[0], ql[1], ql[2], ql[3], kh[j16][1], kh[j16][3]);
            }
        }
        __syncthreads();                 // all warps done reading K tile

        if (t + 1 < NT) load_k((t + 1) << 6);

        // ---- online softmax ----
        float mx0 = -1e30f, mx1 = -1e30f;
#pragma unroll
        for (int j = 0; j < 8; j++) {
            S[j][0] *= scale; S[j][1] *= scale;
            S[j][2] *= scale; S[j][3] *= scale;
            mx0 = fmaxf(mx0, fmaxf(S[j][0], S[j][1]));
            mx1 = fmaxf(mx1, fmaxf(S[j][2], S[j][3]));
        }
        mx0 = fmaxf(mx0, __shfl_xor_sync(0xffffffffu, mx0, 1));
        mx0 = fmaxf(mx0, __shfl_xor_sync(0xffffffffu, mx0, 2));
        mx1 = fmaxf(mx1, __shfl_xor_sync(0xffffffffu, mx1, 1));
        mx1 = fmaxf(mx1, __shfl_xor_sync(0xffffffffu, mx1, 2));

        float mn0 = fmaxf(m0, mx0), mn1 = fmaxf(m1, mx1);
        float fac0 = __expf(m0 - mn0), fac1 = __expf(m1 - mn1);
        float rs0 = 0.f, rs1 = 0.f;
#pragma unroll
        for (int j = 0; j < 8; j++) {
            S[j][0] = __expf(S[j][0] - mn0); rs0 += S[j][0];
            S[j][1] = __expf(S[j][1] - mn0); rs0 += S[j][1];
            S[j][2] = __expf(S[j][2] - mn1); rs1 += S[j][2];
            S[j][3] = __expf(S[j][3] - mn1); rs1 += S[j][3];
        }
        rs0 += __shfl_xor_sync(0xffffffffu, rs0, 1);
        rs0 += __shfl_xor_sync(0xffffffffu, rs0, 2);
        rs1 += __shfl_xor_sync(0xffffffffu, rs1, 1);
        rs1 += __shfl_xor_sync(0xffffffffu, rs1, 2);
        l0 = l0 * fac0 + rs0; m0 = mn0;
        l1 = l1 * fac1 + rs1; m1 = mn1;
#pragma unroll
        for (int n = 0; n < 16; n++) {
            o[n][0] *= fac0; o[n][1] *= fac0;
            o[n][2] *= fac1; o[n][3] *= fac1;
        }

        // ---- V(t) ready? ----
        if (t + 1 < NT) asm volatile("cp.async.wait_group 1;" ::: "memory");
        else            asm volatile("cp.async.wait_group 0;" ::: "memory");
        __syncthreads();

        // ---- O += Ph*Vh + Pl*Vh ----
#pragma unroll
        for (int kk = 0; kk < 4; kk++) {
            uint32_t ah[4], al[4];
            pack_split(S[2*kk][0],   S[2*kk][1],   ah[0], al[0]);
            pack_split(S[2*kk][2],   S[2*kk][3],   ah[1], al[1]);
            pack_split(S[2*kk+1][0], S[2*kk+1][1], ah[2], al[2]);
            pack_split(S[2*kk+1][2], S[2*kk+1][3], ah[3], al[3]);
            const uint32_t vrow = (kk*16 + rsel)*AT_ROWB;
#pragma unroll
            for (int db = 0; db < 8; db += 2) {
                uint32_t vh[2][4];
                ldmatrix_x4_t(vh[0], sVh + vrow + (db*16 + csel)*2);
                ldmatrix_x4_t(vh[1], sVh + vrow + ((db+1)*16 + csel)*2);
#pragma unroll
                for (int u = 0; u < 2; u++) {
                    int n = (db+u)*2;
                    mma16816(o[n],   ah[0], ah[1], ah[2], ah[3], vh[u][0], vh[u][1]);
                    mma16816(o[n+1], ah[0], ah[1], ah[2], ah[3], vh[u][2], vh[u][3]);
                }
#pragma unroll
                for (int u = 0; u < 2; u++) {
                    int n = (db+u)*2;
                    mma16816(o[n],   al[0], al[1], al[2], al[3], vh[u][0], vh[u][1]);
                    mma16816(o[n+1], al[0], al[1], al[2], al[3], vh[u][2], vh[u][3]);
                }
            }
        }
        __syncthreads();                 // all warps done reading V tile

        if (t + 1 < NT) load_v((t + 1) << 6);
    }

    // ---- epilogue: normalize, split to hi/lo fp16, write ctx ----
    const int g  = lane >> 2;
    const int tg = lane & 3;
    const float inv0 = 1.f / l0;
    const float inv1 = 1.f / l1;
    const int s0 = q0 + wq + g;
    const int s1 = s0 + 8;
#pragma unroll
    for (int n = 0; n < 16; n++) {
        int col = h*DD + 8*n + 2*tg;
        {
            size_t off = (size_t)(b*SS + s0) * EE + col;
            __half h0, l0b, h1, l1b;
            split1(o[n][0] * inv0, h0, l0b);
            split1(o[n][1] * inv0, h1, l1b);
            *(__half2*)&g_ch[off] = __halves2half2(h0, h1);
            *(__half2*)&g_cl[off] = __halves2half2(l0b, l1b);
        }
        {
            size_t off = (size_t)(b*SS + s1) * EE + col;
            __half h0, l0b, h1, l1b;
            split1(o[n][2] * inv1, h0, l0b);
            split1(o[n][3] * inv1, h1, l1b);
            *(__half2*)&g_ch[off] = __halves2half2(h0, h1);
            *(__half2*)&g_cl[off] = __halves2half2(l0b, l1b);
        }
    }
}

// ---------------------------------------------------------------------------
// Launch
// ---------------------------------------------------------------------------
extern "C" void kernel_launch(void* const* d_in, const int* in_sizes, int n_in,
                              void* d_out, int out_size)
{
    (void)in_sizes; (void)n_in; (void)out_size;
    const float* x      = (const float*)d_in[0];
    const float* Wqkv_w = (const float*)d_in[1];
    const float* Wqkv_b = (const float*)d_in[2];
    const float* out_w  = (const float*)d_in[3];
    const float* out_b  = (const float*)d_in[4];
    float* out = (float*)d_out;

    __half *xh, *xl, *wqh, *owh, *ch, *cl;
    cudaGetSymbolAddress((void**)&xh,  g_xh);
    cudaGetSymbolAddress((void**)&xl,  g_xl);
    cudaGetSymbolAddress((void**)&wqh, g_wqh);
    cudaGetSymbolAddress((void**)&owh, g_owh);
    cudaGetSymbolAddress((void**)&ch,  g_ch);
    cudaGetSymbolAddress((void**)&cl,  g_cl);

    cudaFuncSetAttribute(attn_mma_kernel, cudaFuncAttributeMaxDynamicSharedMemorySize,
                         ATT_SMEM);
    cudaFuncSetAttribute(gemm_mma<0>, cudaFuncAttributeMaxDynamicSharedMemorySize,
                         GEMM_SMEM);
    cudaFuncSetAttribute(gemm_mma<1>, cudaFuncAttributeMaxDynamicSharedMemorySize,
                         GEMM_SMEM);

    rope_table_kernel<<<(SS * 64 + 255) / 256, 256>>>();

    split_kernel<<<(MTOT*KDIM/4 + 255) / 256, 256>>>(x, xh, xl, MTOT*KDIM);
    cvt_hi_kernel<<<(NQKV*KDIM/4 + 255) / 256, 256>>>(Wqkv_w, wqh, NQKV*KDIM);
    cvt_hi_kernel<<<(EE*KDIM/4 + 255) / 256, 256>>>(out_w, owh, EE*KDIM);

    gemm_mma<0><<<dim3(NQKV/128, MTOT/128), 256, GEMM_SMEM>>>(
        xh, xl, wqh, Wqkv_b, nullptr, MTOT, NQKV, KDIM);

    rope_split_kernel<<<(2 * BB * HH * SS * 64) / 256, 256>>>();

    attn_mma_kernel<<<dim3(SS/128, HH, BB), 256, ATT_SMEM>>>();

    gemm_mma<1><<<dim3(EE/128, MTOT/128), 256, GEMM_SMEM>>>(
        ch, cl, owh, out_b, out, MTOT, EE, KDIM);
}